// round 2
// baseline (speedup 1.0000x reference)
#include <cuda_runtime.h>
#include <math.h>

// Shapes: B=8, E=16, CIN=C=64, H=W=64 (HW=4096)
#define HWSZ 4096
#define BSZ 8
#define ESZ 16
#define CSZ 64

// Scratch (device globals: allocation-free per harness rules)
__device__ float g_V[BSZ*ESZ*CSZ*HWSZ];   // 134 MB
__device__ float g_K[BSZ*ESZ*CSZ*HWSZ];   // 134 MB
__device__ float g_Q[BSZ*ESZ*CSZ*HWSZ];   // 134 MB
__device__ float g_dots[BSZ*CSZ*ESZ*ESZ]; // [b,c,i,j]
__device__ float g_wt[BSZ*CSZ*ESZ*ESZ];   // softmax(dots) over i

__device__ __forceinline__ float selu_f(float x) {
    const float alpha = 1.6732632423543772f;
    const float scale = 1.0507009873554805f;
    return x > 0.f ? scale * x : scale * alpha * expm1f(x);
}

// ---------------------------------------------------------------------------
// K1: fused V/K/Q 1x1-conv. One block = one (b,i) slice x 256-pixel tile.
// x tile [64 cin][256 px] staged in smem once; W (64x64) + bias staged per
// phase; each thread owns 1 pixel, 64 output-channel accumulators in regs.
// out[c] = sum_a W[c,a]*x[a]  (+bias, selu for K/Q).
// ---------------------------------------------------------------------------
__global__ __launch_bounds__(256, 2)
void conv3_kernel(const float* __restrict__ x,
                  const float* __restrict__ Wv, const float* __restrict__ bv,
                  const float* __restrict__ Wk, const float* __restrict__ bk,
                  const float* __restrict__ Wq, const float* __restrict__ bq)
{
    extern __shared__ float smem[];
    float* xs  = smem;              // 64*256 floats
    float* wsm = smem + 64 * 256;   // 64*64 floats
    float* bsm = wsm + 64 * 64;     // 64 floats

    const int t    = threadIdx.x;      // 0..255 = pixel within tile
    const int tile = blockIdx.x;       // 0..15
    const int bi   = blockIdx.y;       // 0..127 = b*16+i

    const size_t sliceBase = (size_t)bi * CSZ * HWSZ + (size_t)tile * 256;
    const float* xin = x + sliceBase;

    // stage x tile: layout xs[a*256 + p]
    for (int j4 = t; j4 < 4096; j4 += 256) {  // 4096 float4 = 64a x 64 p-quads
        int a = j4 >> 6, p4 = j4 & 63;
        *(float4*)(xs + a * 256 + p4 * 4) =
            *(const float4*)(xin + (size_t)a * HWSZ + p4 * 4);
    }

    const float* Wm[3] = {Wv, Wk, Wq};
    const float* Bm[3] = {bv, bk, bq};
    float* Om[3];
    Om[0] = g_V; Om[1] = g_K; Om[2] = g_Q;

    #pragma unroll
    for (int m = 0; m < 3; ++m) {
        __syncthreads();  // previous phase done reading wsm (and x staged)
        for (int jj = t; jj < 4096; jj += 256) wsm[jj] = Wm[m][jj];
        if (t < 64) bsm[t] = Bm[m][t];
        __syncthreads();

        float acc[64];
        #pragma unroll
        for (int c = 0; c < 64; ++c) acc[c] = bsm[c];

        #pragma unroll 4
        for (int a = 0; a < 64; ++a) {
            float xa = xs[a * 256 + t];
            #pragma unroll
            for (int c = 0; c < 64; ++c)
                acc[c] = fmaf(wsm[c * 64 + a], xa, acc[c]);  // W broadcast LDS
        }

        float* op = Om[m] + sliceBase + t;
        if (m == 0) {
            #pragma unroll
            for (int c = 0; c < 64; ++c) op[(size_t)c * HWSZ] = acc[c];
        } else {
            #pragma unroll
            for (int c = 0; c < 64; ++c) op[(size_t)c * HWSZ] = selu_f(acc[c]);
        }
    }
}

// ---------------------------------------------------------------------------
// K2: gram matrix dots[b,c,i,j] = sum_hw K[b,i,c,hw]*Q[b,j,c,hw].
// One block per (b,c); 256 threads = all 16x16 (i,j) pairs; hw in 128-chunks
// staged to smem with stride 132 (bank-conflict-free for the j-strided read).
// ---------------------------------------------------------------------------
__global__ __launch_bounds__(256)
void gram_kernel()
{
    __shared__ __align__(16) float ks[16 * 132];
    __shared__ __align__(16) float qs[16 * 132];

    const int t  = threadIdx.x;
    const int bc = blockIdx.x;            // b*64 + c
    const int i  = t >> 4, j = t & 15;

    const size_t base = (size_t)(bc >> 6) * ESZ * CSZ * HWSZ
                      + (size_t)(bc & 63) * HWSZ;
    const size_t istr = (size_t)CSZ * HWSZ;  // ensemble-member stride

    float acc = 0.f;
    for (int h0 = 0; h0 < HWSZ; h0 += 128) {
        __syncthreads();
        #pragma unroll
        for (int idx = t; idx < 2048; idx += 256) {
            int r = idx >> 7, p = idx & 127;
            ks[r * 132 + p] = g_K[base + (size_t)r * istr + h0 + p];
            qs[r * 132 + p] = g_Q[base + (size_t)r * istr + h0 + p];
        }
        __syncthreads();
        const float* kp = ks + i * 132;
        const float* qp = qs + j * 132;
        #pragma unroll 8
        for (int p = 0; p < 128; p += 2) {
            float2 kv = *(const float2*)(kp + p);
            float2 qv = *(const float2*)(qp + p);
            acc = fmaf(kv.x, qv.x, acc);
            acc = fmaf(kv.y, qv.y, acc);
        }
    }
    g_dots[(size_t)bc * 256 + t] = acc;   // t == i*16+j
}

// ---------------------------------------------------------------------------
// K3: softmax over i for each (b,c,j). 8192 independent rows of 16.
// ---------------------------------------------------------------------------
__global__ __launch_bounds__(256)
void softmax_kernel()
{
    int idx = blockIdx.x * 256 + threadIdx.x;       // (b*64+c)*16 + j
    const float* d = g_dots + (size_t)(idx >> 4) * 256 + (idx & 15);
    float v[16];
    float m = -3.4e38f;
    #pragma unroll
    for (int i = 0; i < 16; ++i) { v[i] = d[i * 16]; m = fmaxf(m, v[i]); }
    float s = 0.f;
    #pragma unroll
    for (int i = 0; i < 16; ++i) { v[i] = expf(v[i] - m); s += v[i]; }
    float inv = 1.f / s;
    float* w = g_wt + (size_t)(idx >> 4) * 256 + (idx & 15);
    #pragma unroll
    for (int i = 0; i < 16; ++i) w[i * 16] = v[i] * inv;
}

// ---------------------------------------------------------------------------
// K4: out[b,j,c,hw] = selu( sum_i w[b,c,i,j] * V[b,i,c,hw] ).
// (mean-centering cancels exactly because softmax weights sum to 1 over i)
// One block per (b,c, 256-pixel chunk); thread = 1 pixel, 16 j-accumulators.
// ---------------------------------------------------------------------------
__global__ __launch_bounds__(256)
void combine_kernel(float* __restrict__ out)
{
    __shared__ float ws[256];
    const int t  = threadIdx.x;
    const int bc = blockIdx.y;   // b*64 + c
    ws[t] = g_wt[(size_t)bc * 256 + t];
    __syncthreads();

    const size_t base = (size_t)(bc >> 6) * ESZ * CSZ * HWSZ
                      + (size_t)(bc & 63) * HWSZ
                      + (size_t)blockIdx.x * 256 + t;
    const size_t istr = (size_t)CSZ * HWSZ;

    float acc[16];
    #pragma unroll
    for (int j = 0; j < 16; ++j) acc[j] = 0.f;

    #pragma unroll
    for (int i = 0; i < 16; ++i) {
        float vi = g_V[base + (size_t)i * istr];
        #pragma unroll
        for (int j = 0; j < 16; ++j)
            acc[j] = fmaf(ws[i * 16 + j], vi, acc[j]);
    }
    #pragma unroll
    for (int j = 0; j < 16; ++j)
        out[base + (size_t)j * istr] = selu_f(acc[j]);
}

// ---------------------------------------------------------------------------
extern "C" void kernel_launch(void* const* d_in, const int* in_sizes, int n_in,
                              void* d_out, int out_size)
{
    const float* x  = (const float*)d_in[0];
    const float* Wv = (const float*)d_in[1];
    const float* bv = (const float*)d_in[2];
    const float* Wk = (const float*)d_in[3];
    const float* bk = (const float*)d_in[4];
    const float* Wq = (const float*)d_in[5];
    const float* bq = (const float*)d_in[6];
    float* out = (float*)d_out;

    const int smem1 = (64 * 256 + 64 * 64 + 64) * (int)sizeof(float); // 82176 B
    cudaFuncSetAttribute(conv3_kernel,
                         cudaFuncAttributeMaxDynamicSharedMemorySize, smem1);

    conv3_kernel<<<dim3(16, 128), 256, smem1>>>(x, Wv, bv, Wk, bk, Wq, bq);
    gram_kernel<<<BSZ * CSZ, 256>>>();
    softmax_kernel<<<(BSZ * CSZ * ESZ) / 256, 256>>>();
    combine_kernel<<<dim3(16, BSZ * CSZ), 256>>>(out);
}

// round 6
// speedup vs baseline: 1.3080x; 1.3080x over previous
#include <cuda_runtime.h>
#include <math.h>

// Shapes: B=8, E=16, CIN=C=64, H=W=64 (HW=4096)
#define HWSZ 4096
#define BSZ 8
#define ESZ 16
#define CSZ 64

// Scratch (device globals: allocation-free per harness rules)
__device__ float g_V[BSZ*ESZ*CSZ*HWSZ];   // 134 MB
__device__ float g_K[BSZ*ESZ*CSZ*HWSZ];   // 134 MB
__device__ float g_Q[BSZ*ESZ*CSZ*HWSZ];   // 134 MB
__device__ float g_dots[BSZ*CSZ*ESZ*ESZ]; // [b,c,i,j]
__device__ float g_wt[BSZ*CSZ*ESZ*ESZ];   // softmax(dots) over i

__device__ __forceinline__ float selu_f(float x) {
    const float alpha = 1.6732632423543772f;
    const float scale = 1.0507009873554805f;
    return x > 0.f ? scale * x : scale * alpha * expm1f(x);
}

// packed fp32x2 FMA (SASS FFMA2; only reachable via PTX fma.rn.f32x2)
#define FMA_F32X2(d, a, b, c) \
    asm("fma.rn.f32x2 %0, %1, %2, %3;" : "=l"(d) : "l"(a), "l"(b), "l"(c))
#define PACK2(d, lo, hi) \
    asm("mov.b64 %0, {%1, %2};" : "=l"(d) : "f"(lo), "f"(hi))
#define DUP2(d, v) \
    asm("mov.b64 %0, {%1, %1};" : "=l"(d) : "f"(v))
#define UNPACK2(lo, hi, d) \
    asm("mov.b64 {%0, %1}, %2;" : "=f"(lo), "=f"(hi) : "l"(d))

// ---------------------------------------------------------------------------
// K1: fused V/K/Q 1x1-conv, FFMA2 version.
// One block = one (b,i) slice x 256-pixel tile. x tile staged once in smem;
// W staged TRANSPOSED (wT[a][c], c-contiguous) so channel-PAIRS load as one
// ld.shared.v2.u64 -> two packed f32x2 operands with zero repack movs.
// Thread = 1 pixel, 32 channel-pair accumulators (64-bit each).
// Inner loop per a: 1 LDS(x) + 1 dup + 16 LDS.128(w) + 32 FFMA2.
// ---------------------------------------------------------------------------
__global__ __launch_bounds__(256, 2)
void conv3_kernel(const float* __restrict__ x,
                  const float* __restrict__ Wv, const float* __restrict__ bv,
                  const float* __restrict__ Wk, const float* __restrict__ bk,
                  const float* __restrict__ Wq, const float* __restrict__ bq)
{
    extern __shared__ float smem[];
    float* xs  = smem;              // 64*256 floats (64 KB)
    float* wTs = smem + 64 * 256;   // 64*64 floats, layout [a][c] (16 KB)
    float* bsm = wTs + 64 * 64;     // 64 floats

    const int t    = threadIdx.x;      // pixel within tile
    const int tile = blockIdx.x;       // 0..15
    const int bi   = blockIdx.y;       // 0..127 = b*16+i

    const size_t sliceBase = (size_t)bi * CSZ * HWSZ + (size_t)tile * 256;
    const float* xin = x + sliceBase;

    // stage x tile: xs[a*256 + p]
    for (int j4 = t; j4 < 4096; j4 += 256) {
        int a = j4 >> 6, p4 = j4 & 63;
        *(float4*)(xs + a * 256 + p4 * 4) =
            *(const float4*)(xin + (size_t)a * HWSZ + p4 * 4);
    }

    const float* Wm[3] = {Wv, Wk, Wq};
    const float* Bm[3] = {bv, bk, bq};
    float* Om[3];
    Om[0] = g_V; Om[1] = g_K; Om[2] = g_Q;

    #pragma unroll
    for (int m = 0; m < 3; ++m) {
        __syncthreads();  // previous phase done reading wTs (and x staged)
        // stage W transposed: wTs[a*64 + c] = W[c*64 + a]
        // (strided global read; W is 16KB and L2-resident across blocks)
        for (int jj = t; jj < 4096; jj += 256) {
            int a = jj >> 6, c = jj & 63;
            wTs[jj] = Wm[m][c * 64 + a];
        }
        if (t < 64) bsm[t] = Bm[m][t];
        __syncthreads();

        unsigned long long acc[32];
        #pragma unroll
        for (int k = 0; k < 32; ++k)
            PACK2(acc[k], bsm[2 * k], bsm[2 * k + 1]);

        #pragma unroll 2
        for (int a = 0; a < 64; ++a) {
            float xa = xs[a * 256 + t];
            unsigned long long xa2;
            DUP2(xa2, xa);
            const ulonglong2* wrow = (const ulonglong2*)(wTs + a * 64);
            #pragma unroll
            for (int k = 0; k < 16; ++k) {
                ulonglong2 w = wrow[k];  // ld.shared.v2.u64: 4 w's, 2 pairs
                FMA_F32X2(acc[2 * k],     w.x, xa2, acc[2 * k]);
                FMA_F32X2(acc[2 * k + 1], w.y, xa2, acc[2 * k + 1]);
            }
        }

        float* op = Om[m] + sliceBase + t;
        if (m == 0) {
            #pragma unroll
            for (int k = 0; k < 32; ++k) {
                float lo, hi;
                UNPACK2(lo, hi, acc[k]);
                op[(size_t)(2 * k) * HWSZ]     = lo;
                op[(size_t)(2 * k + 1) * HWSZ] = hi;
            }
        } else {
            #pragma unroll
            for (int k = 0; k < 32; ++k) {
                float lo, hi;
                UNPACK2(lo, hi, acc[k]);
                op[(size_t)(2 * k) * HWSZ]     = selu_f(lo);
                op[(size_t)(2 * k + 1) * HWSZ] = selu_f(hi);
            }
        }
    }
}

// ---------------------------------------------------------------------------
// K2: gram matrix dots[b,c,i,j] = sum_hw K[b,i,c,hw]*Q[b,j,c,hw].
// One block per (b,c); 256 threads = all 16x16 (i,j) pairs; hw in 128-chunks
// staged to smem (float4) with stride 132 (<=2-way conflicts on the j read).
// ---------------------------------------------------------------------------
__global__ __launch_bounds__(256)
void gram_kernel()
{
    __shared__ __align__(16) float ks[16 * 132];
    __shared__ __align__(16) float qs[16 * 132];

    const int t  = threadIdx.x;
    const int bc = blockIdx.x;            // b*64 + c
    const int i  = t >> 4, j = t & 15;

    const size_t base = (size_t)(bc >> 6) * ESZ * CSZ * HWSZ
                      + (size_t)(bc & 63) * HWSZ;
    const size_t istr = (size_t)CSZ * HWSZ;  // ensemble-member stride

    float acc = 0.f;
    for (int h0 = 0; h0 < HWSZ; h0 += 128) {
        __syncthreads();
        #pragma unroll
        for (int idx = t; idx < 512; idx += 256) {   // 512 float4 = 16r x 32
            int r = idx >> 5, p4 = idx & 31;
            const size_t g = base + (size_t)r * istr + h0 + p4 * 4;
            *(float4*)(ks + r * 132 + p4 * 4) = *(const float4*)(g_K + g);
            *(float4*)(qs + r * 132 + p4 * 4) = *(const float4*)(g_Q + g);
        }
        __syncthreads();
        const float* kp = ks + i * 132;
        const float* qp = qs + j * 132;
        #pragma unroll
        for (int p = 0; p < 128; p += 4) {
            float4 kv = *(const float4*)(kp + p);
            float4 qv = *(const float4*)(qp + p);
            acc = fmaf(kv.x, qv.x, acc);
            acc = fmaf(kv.y, qv.y, acc);
            acc = fmaf(kv.z, qv.z, acc);
            acc = fmaf(kv.w, qv.w, acc);
        }
    }
    g_dots[(size_t)bc * 256 + t] = acc;   // t == i*16+j
}

// ---------------------------------------------------------------------------
// K3: softmax over i for each (b,c,j). 8192 independent rows of 16.
// ---------------------------------------------------------------------------
__global__ __launch_bounds__(256)
void softmax_kernel()
{
    int idx = blockIdx.x * 256 + threadIdx.x;       // (b*64+c)*16 + j
    const float* d = g_dots + (size_t)(idx >> 4) * 256 + (idx & 15);
    float v[16];
    float m = -3.4e38f;
    #pragma unroll
    for (int i = 0; i < 16; ++i) { v[i] = d[i * 16]; m = fmaxf(m, v[i]); }
    float s = 0.f;
    #pragma unroll
    for (int i = 0; i < 16; ++i) { v[i] = expf(v[i] - m); s += v[i]; }
    float inv = 1.f / s;
    float* w = g_wt + (size_t)(idx >> 4) * 256 + (idx & 15);
    #pragma unroll
    for (int i = 0; i < 16; ++i) w[i * 16] = v[i] * inv;
}

// ---------------------------------------------------------------------------
// K4: out[b,j,c,hw] = selu( sum_i w[b,c,i,j] * V[b,i,c,hw] ).
// (mean-centering cancels exactly: softmax weights sum to 1 over i)
// Thread = 4 pixels (float4); LDG.128 in, STG.128 out. DRAM-bound.
// ---------------------------------------------------------------------------
__global__ __launch_bounds__(256)
void combine_kernel(float* __restrict__ out)
{
    __shared__ float ws[256];
    const int t  = threadIdx.x;
    const int bc = blockIdx.y;   // b*64 + c
    ws[t] = g_wt[(size_t)bc * 256 + t];
    __syncthreads();

    const size_t base = (size_t)(bc >> 6) * ESZ * CSZ * HWSZ
                      + (size_t)(bc & 63) * HWSZ
                      + (size_t)blockIdx.x * 1024 + (size_t)t * 4;
    const size_t istr = (size_t)CSZ * HWSZ;

    float4 acc[16];
    #pragma unroll
    for (int j = 0; j < 16; ++j) acc[j] = make_float4(0.f, 0.f, 0.f, 0.f);

    #pragma unroll
    for (int i = 0; i < 16; ++i) {
        float4 vi = *(const float4*)(g_V + base + (size_t)i * istr);
        #pragma unroll
        for (int j = 0; j < 16; ++j) {
            float w = ws[i * 16 + j];
            acc[j].x = fmaf(w, vi.x, acc[j].x);
            acc[j].y = fmaf(w, vi.y, acc[j].y);
            acc[j].z = fmaf(w, vi.z, acc[j].z);
            acc[j].w = fmaf(w, vi.w, acc[j].w);
        }
    }
    #pragma unroll
    for (int j = 0; j < 16; ++j) {
        float4 o;
        o.x = selu_f(acc[j].x);
        o.y = selu_f(acc[j].y);
        o.z = selu_f(acc[j].z);
        o.w = selu_f(acc[j].w);
        *(float4*)(out + base + (size_t)j * istr) = o;
    }
}

// ---------------------------------------------------------------------------
extern "C" void kernel_launch(void* const* d_in, const int* in_sizes, int n_in,
                              void* d_out, int out_size)
{
    const float* x  = (const float*)d_in[0];
    const float* Wv = (const float*)d_in[1];
    const float* bv = (const float*)d_in[2];
    const float* bk = (const float*)d_in[4];
    const float* Wk = (const float*)d_in[3];
    const float* Wq = (const float*)d_in[5];
    const float* bq = (const float*)d_in[6];
    float* out = (float*)d_out;

    const int smem1 = (64 * 256 + 64 * 64 + 64) * (int)sizeof(float); // 82176 B
    cudaFuncSetAttribute(conv3_kernel,
                         cudaFuncAttributeMaxDynamicSharedMemorySize, smem1);

    conv3_kernel<<<dim3(16, 128), 256, smem1>>>(x, Wv, bv, Wk, bk, Wq, bq);
    gram_kernel<<<BSZ * CSZ, 256>>>();
    softmax_kernel<<<(BSZ * CSZ * ESZ) / 256, 256>>>();
    combine_kernel<<<dim3(4, BSZ * CSZ), 256>>>(out);
}

// round 8
// speedup vs baseline: 1.9820x; 1.5154x over previous
#include <cuda_runtime.h>
#include <math.h>

// Shapes: B=8, E=16, CIN=C=64, H=W=64 (HW=4096)
#define HWSZ 4096
#define BSZ 8
#define ESZ 16
#define CSZ 64
#define NCHUNK 8           // gram hw-chunks (512 hw each)

// Scratch (device globals: allocation-free per harness rules)
__device__ float g_V[BSZ*ESZ*CSZ*HWSZ];   // 134 MB
__device__ float g_K[BSZ*ESZ*CSZ*HWSZ];   // 134 MB
__device__ float g_Q[BSZ*ESZ*CSZ*HWSZ];   // 134 MB
__device__ float g_wT[3*CSZ*CSZ];         // W transposed [m][a][c]
__device__ float g_part[NCHUNK*BSZ*CSZ*ESZ*ESZ]; // gram partials [chunk][bc][ij]
__device__ float g_wt[BSZ*CSZ*ESZ*ESZ];   // softmax(dots) over i

__device__ __forceinline__ float selu_f(float x) {
    const float alpha = 1.6732632423543772f;
    const float scale = 1.0507009873554805f;
    return x > 0.f ? scale * x : scale * alpha * expm1f(x);
}

// packed fp32x2 FMA (SASS FFMA2; only reachable via PTX fma.rn.f32x2)
#define FMA_F32X2(d, a, b, c) \
    asm("fma.rn.f32x2 %0, %1, %2, %3;" : "=l"(d) : "l"(a), "l"(b), "l"(c))
#define PACK2(d, lo, hi) \
    asm("mov.b64 %0, {%1, %2};" : "=l"(d) : "f"(lo), "f"(hi))
#define DUP2(d, v) \
    asm("mov.b64 %0, {%1, %1};" : "=l"(d) : "f"(v))
#define UNPACK2(lo, hi, d) \
    asm("mov.b64 {%0, %1}, %2;" : "=f"(lo), "=f"(hi) : "l"(d))

// ---------------------------------------------------------------------------
// K0: prep — transpose the three W matrices once: g_wT[m][a][c] = W[m][c][a].
// ---------------------------------------------------------------------------
__global__ void prep_kernel(const float* __restrict__ Wv,
                            const float* __restrict__ Wk,
                            const float* __restrict__ Wq)
{
    int idx = blockIdx.x * 256 + threadIdx.x;     // 0..12287
    if (idx < 3 * 4096) {
        int m = idx >> 12, r = idx & 4095;
        int a = r >> 6, c = r & 63;
        const float* Wm = (m == 0) ? Wv : (m == 1) ? Wk : Wq;
        g_wT[idx] = Wm[c * 64 + a];
    }
}

// ---------------------------------------------------------------------------
// K1: fused V/K/Q 1x1-conv, FFMA2, 4px x 16ch per thread.
// Block = one (b,i) slice x 256-pixel tile. 256 threads: cg = t>>6 (channel
// group of 16), pq = t&63 (pixel quad). Per a-step per thread:
//   1 LDS.128 (x, 4 px) + 4 broadcast LDS.128 (w, 8 c-pairs) + 4 DUP + 32 FFMA2.
// Stores: 16 STG.128 per phase (4 px contiguous per channel).
// ---------------------------------------------------------------------------
__global__ __launch_bounds__(256, 2)
void conv3_kernel(const float* __restrict__ x,
                  const float* __restrict__ bv,
                  const float* __restrict__ bk,
                  const float* __restrict__ bq)
{
    extern __shared__ float smem[];
    float* xs  = smem;              // 64a*256px floats (64 KB)
    float* wTs = smem + 64 * 256;   // 64a*64c floats (16 KB)
    float* bsm = wTs + 64 * 64;     // 64 floats

    const int t    = threadIdx.x;
    const int pq   = t & 63;            // pixel quad -> px = pq*4
    const int cg   = t >> 6;            // channel group -> c = cg*16..+15
    const int tile = blockIdx.x;        // 0..15
    const int bi   = blockIdx.y;        // 0..127 = b*16+i

    const size_t sliceBase = (size_t)bi * CSZ * HWSZ + (size_t)tile * 256;
    const float* xin = x + sliceBase;

    // stage x tile: xs[a*256 + p], float4, coalesced
    for (int j4 = t; j4 < 4096; j4 += 256) {
        int a = j4 >> 6, p4 = j4 & 63;
        *(float4*)(xs + a * 256 + p4 * 4) =
            *(const float4*)(xin + (size_t)a * HWSZ + p4 * 4);
    }

    const float* Bm[3] = {bv, bk, bq};
    float* Om[3];
    Om[0] = g_V; Om[1] = g_K; Om[2] = g_Q;

    #pragma unroll
    for (int m = 0; m < 3; ++m) {
        __syncthreads();  // previous phase done reading wTs (and x staged)
        // stage pre-transposed W, coalesced float4 (4 per thread)
        {
            const float4* src = (const float4*)(g_wT + m * 4096);
            float4* dst = (float4*)wTs;
            #pragma unroll
            for (int jj = 0; jj < 4; ++jj)
                dst[t + jj * 256] = src[t + jj * 256];
        }
        if (t < 64) bsm[t] = Bm[m][t];
        __syncthreads();

        // acc[p][k]: 4 px x 8 channel-pairs
        unsigned long long acc[4][8];
        #pragma unroll
        for (int k = 0; k < 8; ++k) {
            unsigned long long b2;
            PACK2(b2, bsm[cg * 16 + 2 * k], bsm[cg * 16 + 2 * k + 1]);
            #pragma unroll
            for (int p = 0; p < 4; ++p) acc[p][k] = b2;
        }

        #pragma unroll 2
        for (int a = 0; a < 64; ++a) {
            float4 xv = *(const float4*)(xs + a * 256 + pq * 4);  // 4 px
            unsigned long long xd[4];
            DUP2(xd[0], xv.x); DUP2(xd[1], xv.y);
            DUP2(xd[2], xv.z); DUP2(xd[3], xv.w);
            const ulonglong2* wrow = (const ulonglong2*)(wTs + a * 64 + cg * 16);
            #pragma unroll
            for (int kk = 0; kk < 2; ++kk) {
                ulonglong2 w = wrow[kk];   // broadcast LDS.128: 2 c-pairs
                #pragma unroll
                for (int p = 0; p < 4; ++p) {
                    FMA_F32X2(acc[p][2 * kk],     w.x, xd[p], acc[p][2 * kk]);
                    FMA_F32X2(acc[p][2 * kk + 1], w.y, xd[p], acc[p][2 * kk + 1]);
                }
            }
            const ulonglong2* wrow2 = wrow + 2;
            #pragma unroll
            for (int kk = 0; kk < 2; ++kk) {
                ulonglong2 w = wrow2[kk];
                #pragma unroll
                for (int p = 0; p < 4; ++p) {
                    FMA_F32X2(acc[p][4 + 2 * kk],     w.x, xd[p], acc[p][4 + 2 * kk]);
                    FMA_F32X2(acc[p][4 + 2 * kk + 1], w.y, xd[p], acc[p][4 + 2 * kk + 1]);
                }
            }
        }

        // store: 16 channels x 4 contiguous px -> STG.128 each
        float* op = Om[m] + sliceBase + (size_t)(cg * 16) * HWSZ + pq * 4;
        #pragma unroll
        for (int cc = 0; cc < 16; ++cc) {
            int k = cc >> 1, hi = cc & 1;
            float4 o;
            float v0, v1, v2, v3, dummy;
            if (!hi) {
                UNPACK2(v0, dummy, acc[0][k]); UNPACK2(v1, dummy, acc[1][k]);
                UNPACK2(v2, dummy, acc[2][k]); UNPACK2(v3, dummy, acc[3][k]);
            } else {
                UNPACK2(dummy, v0, acc[0][k]); UNPACK2(dummy, v1, acc[1][k]);
                UNPACK2(dummy, v2, acc[2][k]); UNPACK2(dummy, v3, acc[3][k]);
            }
            if (m == 0) { o.x = v0; o.y = v1; o.z = v2; o.w = v3; }
            else { o.x = selu_f(v0); o.y = selu_f(v1); o.z = selu_f(v2); o.w = selu_f(v3); }
            *(float4*)(op + (size_t)cc * HWSZ) = o;
        }
    }
}

// ---------------------------------------------------------------------------
// K2: gram partials. g_part[ch][bc][i*16+j] = sum_{hw in chunk} K*Q.
// Block = (chunk, bc); 4096 blocks. 256 threads = all (i,j) pairs.
// ---------------------------------------------------------------------------
__global__ __launch_bounds__(256)
void gram_kernel()
{
    __shared__ __align__(16) float ks[16 * 132];
    __shared__ __align__(16) float qs[16 * 132];

    const int t  = threadIdx.x;
    const int ch = blockIdx.x;            // 0..7
    const int bc = blockIdx.y;            // b*64 + c
    const int i  = t >> 4, j = t & 15;

    const size_t base = (size_t)(bc >> 6) * ESZ * CSZ * HWSZ
                      + (size_t)(bc & 63) * HWSZ;
    const size_t istr = (size_t)CSZ * HWSZ;

    float acc = 0.f;
    const int h1 = ch * (HWSZ / NCHUNK);
    for (int h0 = h1; h0 < h1 + HWSZ / NCHUNK; h0 += 128) {
        __syncthreads();
        #pragma unroll
        for (int idx = t; idx < 512; idx += 256) {   // 512 float4 = 16r x 32
            int r = idx >> 5, p4 = idx & 31;
            const size_t g = base + (size_t)r * istr + h0 + p4 * 4;
            *(float4*)(ks + r * 132 + p4 * 4) = *(const float4*)(g_K + g);
            *(float4*)(qs + r * 132 + p4 * 4) = *(const float4*)(g_Q + g);
        }
        __syncthreads();
        const float* kp = ks + i * 132;
        const float* qp = qs + j * 132;
        #pragma unroll
        for (int p = 0; p < 128; p += 4) {
            float4 kv = *(const float4*)(kp + p);
            float4 qv = *(const float4*)(qp + p);
            acc = fmaf(kv.x, qv.x, acc);
            acc = fmaf(kv.y, qv.y, acc);
            acc = fmaf(kv.z, qv.z, acc);
            acc = fmaf(kv.w, qv.w, acc);
        }
    }
    g_part[((size_t)ch * BSZ * CSZ + bc) * 256 + t] = acc;
}

// ---------------------------------------------------------------------------
// K3: chunk-reduce + softmax over i for each (b,c,j). Deterministic.
// ---------------------------------------------------------------------------
__global__ __launch_bounds__(256)
void softmax_kernel()
{
    int idx = blockIdx.x * 256 + threadIdx.x;       // (b*64+c)*16 + j
    const int bc = idx >> 4, j = idx & 15;
    float v[16];
    float m = -3.4e38f;
    #pragma unroll
    for (int i = 0; i < 16; ++i) {
        float s = 0.f;
        #pragma unroll
        for (int ch = 0; ch < NCHUNK; ++ch)
            s += g_part[((size_t)ch * BSZ * CSZ + bc) * 256 + i * 16 + j];
        v[i] = s;
        m = fmaxf(m, s);
    }
    float s = 0.f;
    #pragma unroll
    for (int i = 0; i < 16; ++i) { v[i] = expf(v[i] - m); s += v[i]; }
    float inv = 1.f / s;
    float* w = g_wt + (size_t)bc * 256 + j;
    #pragma unroll
    for (int i = 0; i < 16; ++i) w[i * 16] = v[i] * inv;
}

// ---------------------------------------------------------------------------
// K4: out[b,j,c,hw] = selu( sum_i w[b,c,i,j] * V[b,i,c,hw] ).
// (mean-centering cancels exactly: softmax weights sum to 1 over i)
// Thread = 2 pixels (float2): 32 acc regs -> good occupancy, LDG.64/STG.64.
// ---------------------------------------------------------------------------
__global__ __launch_bounds__(256)
void combine_kernel(float* __restrict__ out)
{
    __shared__ float ws[256];
    const int t  = threadIdx.x;
    const int bc = blockIdx.y;   // b*64 + c
    ws[t] = g_wt[(size_t)bc * 256 + t];
    __syncthreads();

    const size_t base = (size_t)(bc >> 6) * ESZ * CSZ * HWSZ
                      + (size_t)(bc & 63) * HWSZ
                      + (size_t)blockIdx.x * 512 + (size_t)t * 2;
    const size_t istr = (size_t)CSZ * HWSZ;

    float2 acc[16];
    #pragma unroll
    for (int j = 0; j < 16; ++j) acc[j] = make_float2(0.f, 0.f);

    #pragma unroll
    for (int i = 0; i < 16; ++i) {
        float2 vi = *(const float2*)(g_V + base + (size_t)i * istr);
        #pragma unroll
        for (int j = 0; j < 16; ++j) {
            float w = ws[i * 16 + j];
            acc[j].x = fmaf(w, vi.x, acc[j].x);
            acc[j].y = fmaf(w, vi.y, acc[j].y);
        }
    }
    #pragma unroll
    for (int j = 0; j < 16; ++j) {
        float2 o;
        o.x = selu_f(acc[j].x);
        o.y = selu_f(acc[j].y);
        *(float2*)(out + base + (size_t)j * istr) = o;
    }
}

// ---------------------------------------------------------------------------
extern "C" void kernel_launch(void* const* d_in, const int* in_sizes, int n_in,
                              void* d_out, int out_size)
{
    const float* x  = (const float*)d_in[0];
    const float* Wv = (const float*)d_in[1];
    const float* bv = (const float*)d_in[2];
    const float* Wk = (const float*)d_in[3];
    const float* bk = (const float*)d_in[4];
    const float* Wq = (const float*)d_in[5];
    const float* bq = (const float*)d_in[6];
    float* out = (float*)d_out;

    const int smem1 = (64 * 256 + 64 * 64 + 64) * (int)sizeof(float); // 82176 B
    cudaFuncSetAttribute(conv3_kernel,
                         cudaFuncAttributeMaxDynamicSharedMemorySize, smem1);

    prep_kernel<<<48, 256>>>(Wv, Wk, Wq);
    conv3_kernel<<<dim3(16, 128), 256, smem1>>>(x, bv, bk, bq);
    gram_kernel<<<dim3(NCHUNK, BSZ * CSZ), 256>>>();
    softmax_kernel<<<(BSZ * CSZ * ESZ) / 256, 256>>>();
    combine_kernel<<<dim3(8, BSZ * CSZ), 256>>>(out);
}

// round 9
// speedup vs baseline: 2.0321x; 1.0253x over previous
#include <cuda_runtime.h>
#include <math.h>

// Shapes: B=8, E=16, CIN=C=64, H=W=64 (HW=4096)
#define HWSZ 4096
#define BSZ 8
#define ESZ 16
#define CSZ 64
#define NCHUNK 8           // gram hw-chunks (512 hw each)

// Scratch (device globals: allocation-free per harness rules)
__device__ float g_V[BSZ*ESZ*CSZ*HWSZ];   // 134 MB
__device__ float g_K[BSZ*ESZ*CSZ*HWSZ];   // 134 MB
__device__ float g_Q[BSZ*ESZ*CSZ*HWSZ];   // 134 MB
__device__ float g_wT[3*CSZ*CSZ];         // W transposed [m][a][c]
__device__ float g_part[NCHUNK*BSZ*CSZ*ESZ*ESZ]; // gram partials [chunk][bc][ij]
__device__ float g_wt[BSZ*CSZ*ESZ*ESZ];   // softmax(dots) over i

__device__ __forceinline__ float selu_f(float x) {
    const float alpha = 1.6732632423543772f;
    const float scale = 1.0507009873554805f;
    return x > 0.f ? scale * x : scale * alpha * expm1f(x);
}

// packed fp32x2 FMA (SASS FFMA2; only reachable via PTX fma.rn.f32x2)
#define FMA_F32X2(d, a, b, c) \
    asm("fma.rn.f32x2 %0, %1, %2, %3;" : "=l"(d) : "l"(a), "l"(b), "l"(c))
#define PACK2(d, lo, hi) \
    asm("mov.b64 %0, {%1, %2};" : "=l"(d) : "f"(lo), "f"(hi))
#define DUP2(d, v) \
    asm("mov.b64 %0, {%1, %1};" : "=l"(d) : "f"(v))
#define UNPACK2(lo, hi, d) \
    asm("mov.b64 {%0, %1}, %2;" : "=f"(lo), "=f"(hi) : "l"(d))

// ---------------------------------------------------------------------------
// K0: prep — transpose the three W matrices once: g_wT[m][a][c] = W[m][c][a].
// ---------------------------------------------------------------------------
__global__ void prep_kernel(const float* __restrict__ Wv,
                            const float* __restrict__ Wk,
                            const float* __restrict__ Wq)
{
    int idx = blockIdx.x * 256 + threadIdx.x;     // 0..12287
    if (idx < 3 * 4096) {
        int m = idx >> 12, r = idx & 4095;
        int a = r >> 6, c = r & 63;
        const float* Wm = (m == 0) ? Wv : (m == 1) ? Wk : Wq;
        g_wT[idx] = Wm[c * 64 + a];
    }
}

// ---------------------------------------------------------------------------
// K1: fused V/K/Q 1x1-conv, FFMA2, 4px x 16ch per thread.
// All three transposed W's + biases staged ONCE (smem read-only after one
// sync; phases run back-to-back with no further block syncs).
// Per a-step per thread: 1 LDS.128 (x) + 4 DUP + 4 bcast LDS.128 (w) + 32 FFMA2.
// ---------------------------------------------------------------------------
__global__ __launch_bounds__(256, 2)
void conv3_kernel(const float* __restrict__ x,
                  const float* __restrict__ bv,
                  const float* __restrict__ bk,
                  const float* __restrict__ bq)
{
    extern __shared__ float smem[];
    float* xs  = smem;                   // 64a*256px (64 KB)
    float* wTs = smem + 64 * 256;        // 3*64a*64c (48 KB)
    float* bsm = wTs + 3 * 64 * 64;      // 3*64 floats

    const int t    = threadIdx.x;
    const int pq   = t & 63;            // pixel quad -> px = pq*4
    const int cg   = t >> 6;            // channel group -> c = cg*16..+15
    const int tile = blockIdx.x;        // 0..15
    const int bi   = blockIdx.y;        // 0..127 = b*16+i

    const size_t sliceBase = (size_t)bi * CSZ * HWSZ + (size_t)tile * 256;
    const float* xin = x + sliceBase;

    // stage x tile: xs[a*256 + p], float4, coalesced
    for (int j4 = t; j4 < 4096; j4 += 256) {
        int a = j4 >> 6, p4 = j4 & 63;
        *(float4*)(xs + a * 256 + p4 * 4) =
            *(const float4*)(xin + (size_t)a * HWSZ + p4 * 4);
    }
    // stage all three pre-transposed W's (coalesced float4, 12 per thread)
    {
        const float4* src = (const float4*)g_wT;
        float4* dst = (float4*)wTs;
        #pragma unroll
        for (int jj = 0; jj < 12; ++jj)
            dst[t + jj * 256] = src[t + jj * 256];
    }
    if (t < 192) bsm[t] = (t < 64) ? bv[t] : (t < 128) ? bk[t - 64] : bq[t - 128];
    __syncthreads();

    float* Om[3];
    Om[0] = g_V; Om[1] = g_K; Om[2] = g_Q;

    #pragma unroll
    for (int m = 0; m < 3; ++m) {
        const float* wm = wTs + m * 4096;
        const float* bm = bsm + m * 64;

        // acc[p][k]: 4 px x 8 channel-pairs
        unsigned long long acc[4][8];
        #pragma unroll
        for (int k = 0; k < 8; ++k) {
            unsigned long long b2;
            PACK2(b2, bm[cg * 16 + 2 * k], bm[cg * 16 + 2 * k + 1]);
            #pragma unroll
            for (int p = 0; p < 4; ++p) acc[p][k] = b2;
        }

        #pragma unroll 2
        for (int a = 0; a < 64; ++a) {
            float4 xv = *(const float4*)(xs + a * 256 + pq * 4);  // 4 px
            unsigned long long xd[4];
            DUP2(xd[0], xv.x); DUP2(xd[1], xv.y);
            DUP2(xd[2], xv.z); DUP2(xd[3], xv.w);
            const ulonglong2* wrow = (const ulonglong2*)(wm + a * 64 + cg * 16);
            #pragma unroll
            for (int kk = 0; kk < 4; ++kk) {
                ulonglong2 w = wrow[kk];   // broadcast LDS.128: 2 c-pairs
                #pragma unroll
                for (int p = 0; p < 4; ++p) {
                    FMA_F32X2(acc[p][2 * kk],     w.x, xd[p], acc[p][2 * kk]);
                    FMA_F32X2(acc[p][2 * kk + 1], w.y, xd[p], acc[p][2 * kk + 1]);
                }
            }
        }

        // store: 16 channels x 4 contiguous px -> STG.128 each
        float* op = Om[m] + sliceBase + (size_t)(cg * 16) * HWSZ + pq * 4;
        #pragma unroll
        for (int cc = 0; cc < 16; ++cc) {
            int k = cc >> 1, hi = cc & 1;
            float4 o;
            float v0, v1, v2, v3, dummy;
            if (!hi) {
                UNPACK2(v0, dummy, acc[0][k]); UNPACK2(v1, dummy, acc[1][k]);
                UNPACK2(v2, dummy, acc[2][k]); UNPACK2(v3, dummy, acc[3][k]);
            } else {
                UNPACK2(dummy, v0, acc[0][k]); UNPACK2(dummy, v1, acc[1][k]);
                UNPACK2(dummy, v2, acc[2][k]); UNPACK2(dummy, v3, acc[3][k]);
            }
            if (m == 0) { o.x = v0; o.y = v1; o.z = v2; o.w = v3; }
            else { o.x = selu_f(v0); o.y = selu_f(v1); o.z = selu_f(v2); o.w = selu_f(v3); }
            *(float4*)(op + (size_t)cc * HWSZ) = o;
        }
    }
}

// ---------------------------------------------------------------------------
// K2: gram partials. g_part[ch][bc][i*16+j] = sum_{hw in chunk} K*Q.
// Block = (chunk, bc); 4096 blocks. 256 threads = all (i,j) pairs.
// ---------------------------------------------------------------------------
__global__ __launch_bounds__(256)
void gram_kernel()
{
    __shared__ __align__(16) float ks[16 * 132];
    __shared__ __align__(16) float qs[16 * 132];

    const int t  = threadIdx.x;
    const int ch = blockIdx.x;            // 0..7
    const int bc = blockIdx.y;            // b*64 + c
    const int i  = t >> 4, j = t & 15;

    const size_t base = (size_t)(bc >> 6) * ESZ * CSZ * HWSZ
                      + (size_t)(bc & 63) * HWSZ;
    const size_t istr = (size_t)CSZ * HWSZ;

    float acc = 0.f;
    const int h1 = ch * (HWSZ / NCHUNK);
    for (int h0 = h1; h0 < h1 + HWSZ / NCHUNK; h0 += 128) {
        __syncthreads();
        #pragma unroll
        for (int idx = t; idx < 512; idx += 256) {   // 512 float4 = 16r x 32
            int r = idx >> 5, p4 = idx & 31;
            const size_t g = base + (size_t)r * istr + h0 + p4 * 4;
            *(float4*)(ks + r * 132 + p4 * 4) = *(const float4*)(g_K + g);
            *(float4*)(qs + r * 132 + p4 * 4) = *(const float4*)(g_Q + g);
        }
        __syncthreads();
        const float* kp = ks + i * 132;
        const float* qp = qs + j * 132;
        #pragma unroll
        for (int p = 0; p < 128; p += 4) {
            float4 kv = *(const float4*)(kp + p);
            float4 qv = *(const float4*)(qp + p);
            acc = fmaf(kv.x, qv.x, acc);
            acc = fmaf(kv.y, qv.y, acc);
            acc = fmaf(kv.z, qv.z, acc);
            acc = fmaf(kv.w, qv.w, acc);
        }
    }
    g_part[((size_t)ch * BSZ * CSZ + bc) * 256 + t] = acc;
}

// ---------------------------------------------------------------------------
// K3: chunk-reduce + softmax, one block per bc (512 blocks, coalesced).
// t = i*16+j. Reduce 8 chunk partials (t-contiguous loads), then softmax
// over i per column j via two smem passes. Deterministic.
// ---------------------------------------------------------------------------
__global__ __launch_bounds__(256)
void softmax_kernel()
{
    __shared__ float dots[256];
    __shared__ float es[256];
    const int t  = threadIdx.x;
    const int bc = blockIdx.x;
    const int j  = t & 15;

    float s = 0.f;
    #pragma unroll
    for (int ch = 0; ch < NCHUNK; ++ch)
        s += g_part[((size_t)ch * BSZ * CSZ + bc) * 256 + t];
    dots[t] = s;
    __syncthreads();

    float m = -3.4e38f;
    #pragma unroll
    for (int ii = 0; ii < 16; ++ii) m = fmaxf(m, dots[ii * 16 + j]);
    float e = expf(s - m);
    es[t] = e;
    __syncthreads();

    float sum = 0.f;
    #pragma unroll
    for (int ii = 0; ii < 16; ++ii) sum += es[ii * 16 + j];
    g_wt[(size_t)bc * 256 + t] = e / sum;
}

// ---------------------------------------------------------------------------
// K4: out[b,j,c,hw] = selu( sum_i w[b,c,i,j] * V[b,i,c,hw] ).
// (mean-centering cancels exactly: softmax weights sum to 1 over i)
// Thread = 2 pixels (float2): lean regs -> good occupancy.
// ---------------------------------------------------------------------------
__global__ __launch_bounds__(256)
void combine_kernel(float* __restrict__ out)
{
    __shared__ float ws[256];
    const int t  = threadIdx.x;
    const int bc = blockIdx.y;   // b*64 + c
    ws[t] = g_wt[(size_t)bc * 256 + t];
    __syncthreads();

    const size_t base = (size_t)(bc >> 6) * ESZ * CSZ * HWSZ
                      + (size_t)(bc & 63) * HWSZ
                      + (size_t)blockIdx.x * 512 + (size_t)t * 2;
    const size_t istr = (size_t)CSZ * HWSZ;

    float2 acc[16];
    #pragma unroll
    for (int j = 0; j < 16; ++j) acc[j] = make_float2(0.f, 0.f);

    #pragma unroll
    for (int i = 0; i < 16; ++i) {
        float2 vi = *(const float2*)(g_V + base + (size_t)i * istr);
        #pragma unroll
        for (int j = 0; j < 16; ++j) {
            float w = ws[i * 16 + j];
            acc[j].x = fmaf(w, vi.x, acc[j].x);
            acc[j].y = fmaf(w, vi.y, acc[j].y);
        }
    }
    #pragma unroll
    for (int j = 0; j < 16; ++j) {
        float2 o;
        o.x = selu_f(acc[j].x);
        o.y = selu_f(acc[j].y);
        *(float2*)(out + base + (size_t)j * istr) = o;
    }
}

// ---------------------------------------------------------------------------
extern "C" void kernel_launch(void* const* d_in, const int* in_sizes, int n_in,
                              void* d_out, int out_size)
{
    const float* x  = (const float*)d_in[0];
    const float* Wv = (const float*)d_in[1];
    const float* bv = (const float*)d_in[2];
    const float* Wk = (const float*)d_in[3];
    const float* bk = (const float*)d_in[4];
    const float* Wq = (const float*)d_in[5];
    const float* bq = (const float*)d_in[6];
    float* out = (float*)d_out;

    const int smem1 = (64 * 256 + 3 * 64 * 64 + 192) * (int)sizeof(float); // 115456 B
    cudaFuncSetAttribute(conv3_kernel,
                         cudaFuncAttributeMaxDynamicSharedMemorySize, smem1);

    prep_kernel<<<48, 256>>>(Wv, Wk, Wq);
    conv3_kernel<<<dim3(16, 128), 256, smem1>>>(x, bv, bk, bq);
    gram_kernel<<<dim3(NCHUNK, BSZ * CSZ), 256>>>();
    softmax_kernel<<<BSZ * CSZ, 256>>>();
    combine_kernel<<<dim3(8, BSZ * CSZ), 256>>>(out);
}